// round 1
// baseline (speedup 1.0000x reference)
#include <cuda_runtime.h>
#include <math_constants.h>

// Problem constants
#define B_ 32
#define L_ 8192
#define C_ 256
#define S_ 64              // L-splits
#define CHUNK_ (L_ / S_)   // 128 elements per thread

// Scratch for partial results: [B*S, C, 6] = 12 MB (device global, no alloc)
__device__ float g_part[(size_t)B_ * S_ * C_ * 6];

__device__ __forceinline__ void track(float v,
                                      float& mx0, float& mx1, float& mx2,
                                      float& mn0, float& mn1, float& mn2) {
    // top-3 max (mx0 >= mx1 >= mx2)
    if (v > mx2) {
        if (v > mx0)      { mx2 = mx1; mx1 = mx0; mx0 = v; }
        else if (v > mx1) { mx2 = mx1; mx1 = v; }
        else              { mx2 = v; }
    }
    // top-3 min (mn0 <= mn1 <= mn2)
    if (v < mn2) {
        if (v < mn0)      { mn2 = mn1; mn1 = mn0; mn0 = v; }
        else if (v < mn1) { mn2 = mn1; mn1 = v; }
        else              { mn2 = v; }
    }
}

// Pass 1: each block = (l-chunk s, batch b), each thread owns one channel c.
// Warp reads 32 consecutive fp32 along c => fully coalesced 128B lines.
__global__ __launch_bounds__(C_) void kmm_partial(const float* __restrict__ x) {
    const int c = threadIdx.x;
    const int s = blockIdx.x;
    const int b = blockIdx.y;

    const float* __restrict__ p =
        x + ((size_t)b * L_ + (size_t)s * CHUNK_) * C_ + c;

    float mx0 = -CUDART_INF_F, mx1 = -CUDART_INF_F, mx2 = -CUDART_INF_F;
    float mn0 =  CUDART_INF_F, mn1 =  CUDART_INF_F, mn2 =  CUDART_INF_F;

    // MLP=8: batch 8 independent loads, then update trackers
    for (int l = 0; l < CHUNK_; l += 8) {
        float v[8];
#pragma unroll
        for (int j = 0; j < 8; j++)
            v[j] = __ldg(p + (size_t)(l + j) * C_);
#pragma unroll
        for (int j = 0; j < 8; j++)
            track(v[j], mx0, mx1, mx2, mn0, mn1, mn2);
    }

    float* o = g_part + (((size_t)(b * S_ + s)) * C_ + c) * 6;
    o[0] = mn0; o[1] = mn1; o[2] = mn2;
    o[3] = mx0; o[4] = mx1; o[5] = mx2;
}

// Pass 2: one thread per (b, c) row merges S_ sorted partial triples.
__global__ __launch_bounds__(256) void kmm_reduce(float* __restrict__ out) {
    const int idx = blockIdx.x * blockDim.x + threadIdx.x;  // b*C + c
    if (idx >= B_ * C_) return;
    const int b = idx / C_;
    const int c = idx % C_;

    float mx0 = -CUDART_INF_F, mx1 = -CUDART_INF_F, mx2 = -CUDART_INF_F;
    float mn0 =  CUDART_INF_F, mn1 =  CUDART_INF_F, mn2 =  CUDART_INF_F;

    for (int s = 0; s < S_; s++) {
        const float* o = g_part + (((size_t)(b * S_ + s)) * C_ + c) * 6;
        float p0 = o[0], p1 = o[1], p2 = o[2];
        float q0 = o[3], q1 = o[4], q2 = o[5];
        // min candidates
        if (p0 < mn2) {
            if (p0 < mn0)      { mn2 = mn1; mn1 = mn0; mn0 = p0; }
            else if (p0 < mn1) { mn2 = mn1; mn1 = p0; }
            else               { mn2 = p0; }
        }
        if (p1 < mn2) {
            if (p1 < mn0)      { mn2 = mn1; mn1 = mn0; mn0 = p1; }
            else if (p1 < mn1) { mn2 = mn1; mn1 = p1; }
            else               { mn2 = p1; }
        }
        if (p2 < mn2) {
            if (p2 < mn0)      { mn2 = mn1; mn1 = mn0; mn0 = p2; }
            else if (p2 < mn1) { mn2 = mn1; mn1 = p2; }
            else               { mn2 = p2; }
        }
        // max candidates
        if (q0 > mx2) {
            if (q0 > mx0)      { mx2 = mx1; mx1 = mx0; mx0 = q0; }
            else if (q0 > mx1) { mx2 = mx1; mx1 = q0; }
            else               { mx2 = q0; }
        }
        if (q1 > mx2) {
            if (q1 > mx0)      { mx2 = mx1; mx1 = mx0; mx0 = q1; }
            else if (q1 > mx1) { mx2 = mx1; mx1 = q1; }
            else               { mx2 = q1; }
        }
        if (q2 > mx2) {
            if (q2 > mx0)      { mx2 = mx1; mx1 = mx0; mx0 = q2; }
            else if (q2 > mx1) { mx2 = mx1; mx1 = q2; }
            else               { mx2 = q2; }
        }
    }

    float* r = out + (size_t)idx * 6;
    r[0] = mn0; r[1] = mn1; r[2] = mn2;
    r[3] = mx0; r[4] = mx1; r[5] = mx2;
}

extern "C" void kernel_launch(void* const* d_in, const int* in_sizes, int n_in,
                              void* d_out, int out_size) {
    const float* x = (const float*)d_in[0];
    float* out = (float*)d_out;

    dim3 grid1(S_, B_);
    kmm_partial<<<grid1, C_>>>(x);

    const int total = B_ * C_;
    kmm_reduce<<<(total + 255) / 256, 256>>>(out);
}